// round 16
// baseline (speedup 1.0000x reference)
#include <cuda_runtime.h>
#include <cstdint>

#define N 160
#define NDIAG (2 * N - 1)   // 319 anti-diagonals, 0-based s = ri + c
#define PCELLS (320 * N)    // fixed-stride per-problem scratch (slot per diag)
#define BC 512
#define CH 8
#define BATCH 64
#define SLOT 161            // ring slot entries (161st = garbage pad for ri+1)
#define BIGV 1e10f
#define FULLM 0xffffffffu

// exp/log folding constants (gamma = 0.01)
#define KLOG2E 144.26950408889634f      // (1/GAMMA) * log2(e)
#define NEGK (-144.26950408889634f)
#define NGLN2 (-0.006931471805599453f)  // -GAMMA * ln(2)

// Softmin gradient weights: (wd, wu); wl = 1 - wd - wu.
// Fixed-stride diag-major: problem p, diag d, row ri -> p*PCELLS + d*N + ri.
__device__ float2 g_w2[(size_t)BC * PCELLS + 256];
__device__ float g_sdtw[BC];
__device__ float g_lt[BC];
__device__ unsigned g_ticket;  // zero-init; last block resets -> replay-safe

__device__ __forceinline__ float ex2f(float x) {
    float r;
    asm("ex2.approx.f32 %0, %1;" : "=f"(r) : "f"(x));
    return r;
}
__device__ __forceinline__ float lg2f(float x) {
    float r;
    asm("lg2.approx.f32 %0, %1;" : "=f"(r) : "f"(x));
    return r;
}
__device__ __forceinline__ float rcpf(float x) {
    float r;
    asm("rcp.approx.f32 %0, %1;" : "=f"(r) : "f"(x));
    return r;
}
__device__ __forceinline__ uint32_t smem_u32(const void* p) {
    return (uint32_t)__cvta_generic_to_shared(p);
}
__device__ __forceinline__ void cpa8(uint32_t dst, const void* src) {
    asm volatile("cp.async.ca.shared.global [%0], [%1], 8;" ::"r"(dst),
                 "l"(src));
}
#define CP_COMMIT() asm volatile("cp.async.commit_group;" ::: "memory")
#define CP_WAIT6() asm volatile("cp.async.wait_group 6;" ::: "memory")

// Branch-free predicated store of a float2 (predicated-off -> no mem access).
__device__ __forceinline__ void st_pred2(unsigned act, float2* ptr, float x,
                                         float y) {
    asm volatile(
        "{\n\t.reg .pred p;\n\tsetp.ne.u32 p, %0, 0;\n\t"
        "@p st.global.v2.f32 [%1], {%2, %3};\n\t}"
        ::"r"(act), "l"(ptr), "f"(x), "f"(y)
        : "memory");
}

__global__ __launch_bounds__(128) void dtw_warp_kernel(
    const float* __restrict__ input, const float* __restrict__ target,
    float* __restrict__ out) {
    const int lane = threadIdx.x & 31;
    const int w = threadIdx.x >> 5;
    const int prob = blockIdx.x * 4 + w;  // 1 warp = 1 problem

    __shared__ float sp_s[4][256];     // input row, 256 so (c & 255) is safe
    __shared__ float2 ring[4][8][SLOT];  // per-warp 8-slot diagonal ring
    __shared__ unsigned s_last;
    __shared__ float ws[4];

    for (int k = lane; k < N; k += 32) sp_s[w][k] = input[prob * N + k];
    float st5[5];
#pragma unroll
    for (int g = 0; g < 5; ++g) st5[g] = target[prob * N + lane + 32 * g];
    __syncwarp();

    const float* spw = sp_s[w];
    float2* const pwbase = g_w2 + (size_t)prob * PCELLS + lane;
    float Rcur[5], uprev[5];
#pragma unroll
    for (int g = 0; g < 5; ++g) { Rcur[g] = BIGV; uprev[g] = BIGV; }

    // ---------------- forward: branch-free shuffle wavefront ----------------
    // Inactive lanes compute harmless garbage; only the STG is predicated.
    {
        float2* pw = pwbase;  // diag s row base (+lane)
        for (int s = 0; s < NDIAG; ++s) {
            float u[5];
#pragma unroll
            for (int g = 0; g < 5; ++g)
                u[g] = __shfl_sync(FULLM, Rcur[g], (lane + 31) & 31);
#pragma unroll
            for (int g = 0; g < 5; ++g) {
                const int ri = lane + 32 * g;
                const int c = s - ri;
                const unsigned act = (unsigned)c < (unsigned)N;
                float upv, dg;
                if (g == 0) {
                    const bool l0 = (lane == 0);
                    upv = l0 ? BIGV : u[0];
                    dg = (c == 0) ? (l0 ? 0.0f : BIGV) : (l0 ? BIGV : uprev[0]);
                } else {
                    upv = (lane == 0) ? u[g - 1] : u[g];
                    dg = (c == 0) ? BIGV : uprev[g];
                }
                const float lf = (c == 0) ? BIGV : Rcur[g];
                const float diff = st5[g] - spw[c & 255];
                const float d = diff * diff;
                const float mn = fminf(dg, fminf(upv, lf));
                const float mnK = mn * KLOG2E;
                const float ea = ex2f(fmaf(dg, NEGK, mnK));
                const float eb = ex2f(fmaf(upv, NEGK, mnK));
                const float ec = ex2f(fmaf(lf, NEGK, mnK));
                const float ssum = ea + eb + ec;
                const float r = fmaf(NGLN2, lg2f(ssum), d + mn);
                const float inv = rcpf(ssum);
                st_pred2(act, pw + 32 * g, ea * inv, eb * inv);
                uprev[g] = upv;
                Rcur[g] = r;
            }
            pw += N;
        }
    }
    if (lane == 31) g_sdtw[prob] = Rcur[4];  // R[N-1][N-1]

    __threadfence_block();  // order weight stores before cp.async readback

    // ---------------- backward: branch-free reverse wavefront ----------------
    float2* const ringw = &ring[w][0][0];
    auto prefetch = [&](int d) {
        const float2* src = pwbase + d * N;
        uint32_t dst = smem_u32(ringw + (d & 7) * SLOT + lane);
#pragma unroll
        for (int k = 0; k < 5; ++k)
            cpa8(dst + (uint32_t)(k * 32 * sizeof(float2)), src + k * 32);
        CP_COMMIT();
    };
#pragma unroll
    for (int d = NDIAG - 1; d >= NDIAG - 7; --d) prefetch(d);  // 318..312

    float Ecur[5], dprev[5], ddf[5];
#pragma unroll
    for (int g = 0; g < 5; ++g) {
        Ecur[g] = 0.0f;
        dprev[g] = 0.0f;
        // ri - c at sb = 317: 2*ri - 317
        ddf[g] = (float)(2 * (lane + 32 * g) - (NDIAG - 2));
    }
    Ecur[4] = (lane == 31) ? 1.0f : 0.0f;  // seed E[N-1][N-1] (sb = 318)
    float acc = 0.0f;                       // seed contributes 0 (ri == c)

    for (int sb = NDIAG - 2; sb >= 0; --sb) {
        CP_WAIT6();  // diag sb+1 (and older) staged
        float sd[5];
#pragma unroll
        for (int g = 0; g < 5; ++g)
            sd[g] = __shfl_sync(FULLM, Ecur[g], (lane + 1) & 31);
        const float2* ch1 = ringw + ((sb + 1) & 7) * SLOT;
        const float2* ch2 = ringw + ((sb + 2) & 7) * SLOT;
#pragma unroll
        for (int g = 0; g < 5; ++g) {
            const int ri = lane + 32 * g;
            const int c = sb - ri;
            const unsigned act = (unsigned)c < (unsigned)N;
            const float echild =
                (lane < 31) ? sd[g] : ((g < 4) ? sd[g + 1] : 0.0f);
            const float2 f = ch1[ri + 1];  // child (ri+1, c):   wu
            const float2 q = ch1[ri];      // child (ri, c+1):   wl
            const float2 h = ch2[ri + 1];  // child (ri+1, c+1): wd
            const bool rok = (ri + 1 < N);
            const bool cok = (c + 1 < N);
            const float wuv = rok ? f.y : 0.0f;
            const float wlv = cok ? (1.0f - q.x - q.y) : 0.0f;
            const float wdv = (rok && cok) ? h.x : 0.0f;
            float ev = echild * wuv;
            ev = fmaf(dprev[g], wdv, ev);
            ev = fmaf(Ecur[g], wlv, ev);
            dprev[g] = echild;
            Ecur[g] = ev;
            const float evm = act ? ev : 0.0f;
            acc = fmaf(evm * ddf[g], ddf[g], acc);
            ddf[g] += 1.0f;
        }
        prefetch(max(sb - 6, 0));  // clamped re-fetch near sb=0 is harmless
    }

    // warp reduction of temporal accumulator
#pragma unroll
    for (int o = 16; o; o >>= 1) acc += __shfl_down_sync(FULLM, acc, o);
    if (lane == 0) g_lt[prob] = acc * (1.0f / (float)(N * N));

    // ---------------- fused final reduction (last block) ----------------
    __threadfence();  // publish g_sdtw / g_lt
    __syncthreads();
    if (threadIdx.x == 0)
        s_last = (atomicAdd(&g_ticket, 1u) == (unsigned)(gridDim.x - 1));
    __syncthreads();
    if (s_last) {
        const int b = threadIdx.x;  // 0..127; only 0..63 carry a batch
        float ls = 0.0f, lt = 0.0f;
        if (b < BATCH) {
#pragma unroll
            for (int c = 0; c < CH; ++c) {
                ls += g_sdtw[b * CH + c];
                lt += g_lt[b * CH + c];
            }
            ls *= (1.0f / (float)CH);
            lt *= (1.0f / (float)CH);
            out[1 + b] = ls;          // loss_shape
            out[1 + BATCH + b] = lt;  // loss_temporal
        }
        float v = (b < BATCH) ? (0.5f * ls + 0.5f * lt) : 0.0f;
#pragma unroll
        for (int o = 16; o; o >>= 1) v += __shfl_down_sync(FULLM, v, o);
        if ((threadIdx.x & 31) == 0) ws[threadIdx.x >> 5] = v;
        __syncthreads();
        if (threadIdx.x == 0) {
            out[0] = (ws[0] + ws[1]) * (1.0f / (float)BATCH);  // loss
            g_ticket = 0;  // reset for next graph replay
        }
    }
}

extern "C" void kernel_launch(void* const* d_in, const int* in_sizes, int n_in,
                              void* d_out, int out_size) {
    const float* input = (const float*)d_in[0];
    const float* target = (const float*)d_in[1];
    float* out = (float*)d_out;
    dtw_warp_kernel<<<BC / 4, 128>>>(input, target, out);
}

// round 17
// speedup vs baseline: 1.0911x; 1.0911x over previous
#include <cuda_runtime.h>
#include <cstdint>

#define N 160
#define NCELLS (N * N)
#define NDIAG (2 * N - 1)  // 319 anti-diagonals, 0-based s = ri + c
#define BC 512
#define CH 8
#define BATCH 64
#define SLOT 162  // ring slot: [front pad][0..159][overread pad]
#define BIGV 1e10f
#define FULLM 0xffffffffu

// exp/log folding constants (gamma = 0.01)
#define KLOG2E 144.26950408889634f      // (1/GAMMA) * log2(e)
#define NEGK (-144.26950408889634f)
#define NGLN2 (-0.006931471805599453f)  // -GAMMA * ln(2)

// Softmin gradient weights: (wd, wu); wl = 1 - wd - wu.
// Diag-major COMPACTED (105 MB -> L2-resident with LIFO reuse).
// +256 cells pad so fixed 160-entry prefetches may overrun the tail.
__device__ float2 g_w2[(size_t)BC * NCELLS + 256];
__device__ float g_sdtw[BC];
__device__ float g_lt[BC];
__device__ unsigned g_ticket;  // zero-init; last block resets -> replay-safe

__device__ __forceinline__ int doffs(int s) {  // cells preceding diag s
    return (s <= 160) ? (s * (s + 1)) / 2
                      : NCELLS - ((319 - s) * (320 - s)) / 2;
}

__device__ __forceinline__ float ex2f(float x) {
    float r;
    asm("ex2.approx.f32 %0, %1;" : "=f"(r) : "f"(x));
    return r;
}
__device__ __forceinline__ float lg2f(float x) {
    float r;
    asm("lg2.approx.f32 %0, %1;" : "=f"(r) : "f"(x));
    return r;
}
__device__ __forceinline__ float rcpf(float x) {
    float r;
    asm("rcp.approx.f32 %0, %1;" : "=f"(r) : "f"(x));
    return r;
}
__device__ __forceinline__ uint32_t smem_u32(const void* p) {
    return (uint32_t)__cvta_generic_to_shared(p);
}
__device__ __forceinline__ void cpa8(uint32_t dst, const void* src) {
    asm volatile("cp.async.ca.shared.global [%0], [%1], 8;" ::"r"(dst),
                 "l"(src));
}
#define CP_COMMIT() asm volatile("cp.async.commit_group;" ::: "memory")
#define CP_WAIT6() asm volatile("cp.async.wait_group 6;" ::: "memory")

// Branch-free predicated store of a float2 (predicated-off -> no mem access).
__device__ __forceinline__ void st_pred2(unsigned act, float2* ptr, float x,
                                         float y) {
    asm volatile(
        "{\n\t.reg .pred p;\n\tsetp.ne.u32 p, %0, 0;\n\t"
        "@p st.global.v2.f32 [%1], {%2, %3};\n\t}"
        ::"r"(act), "l"(ptr), "f"(x), "f"(y)
        : "memory");
}

__global__ __launch_bounds__(128) void dtw_warp_kernel(
    const float* __restrict__ input, const float* __restrict__ target,
    float* __restrict__ out) {
    const int lane = threadIdx.x & 31;
    const int w = threadIdx.x >> 5;
    const int prob = blockIdx.x * 4 + w;  // 1 warp = 1 problem

    __shared__ float sp_s[4][256];        // padded so (c & 255) is mem-safe
    __shared__ float2 ring[4][8][SLOT];   // per-warp 8-slot diagonal ring
    __shared__ unsigned s_last;
    __shared__ float ws[4];

    for (int k = lane; k < N; k += 32) sp_s[w][k] = input[prob * N + k];
    float st5[5];
#pragma unroll
    for (int g = 0; g < 5; ++g) st5[g] = target[prob * N + lane + 32 * g];
    __syncwarp();

    const float* spw = sp_s[w];
    float2* const probbase = g_w2 + (size_t)prob * NCELLS;
    float Rcur[5], uprev[5];
#pragma unroll
    for (int g = 0; g < 5; ++g) { Rcur[g] = BIGV; uprev[g] = BIGV; }

    // ---------------- forward: branch-free shuffle wavefront ----------------
    // Store addr for cell (ri, diag s) = probbase + A(s) + ri,
    // A(s) = doffs(s) - rlo(s), carried incrementally.
    {
        float2* pw = probbase + lane;  // A(0) = 0
        for (int s = 0; s < NDIAG; ++s) {
            float u[5];
#pragma unroll
            for (int g = 0; g < 5; ++g)
                u[g] = __shfl_sync(FULLM, Rcur[g], (lane + 31) & 31);
#pragma unroll
            for (int g = 0; g < 5; ++g) {
                const int ri = lane + 32 * g;
                const int c = s - ri;
                const unsigned act = (unsigned)c < (unsigned)N;
                float upv, dg;
                if (g == 0) {
                    const bool l0 = (lane == 0);
                    upv = l0 ? BIGV : u[0];
                    dg = (c == 0) ? (l0 ? 0.0f : BIGV) : (l0 ? BIGV : uprev[0]);
                } else {
                    upv = (lane == 0) ? u[g - 1] : u[g];
                    dg = (c == 0) ? BIGV : uprev[g];
                }
                const float lf = (c == 0) ? BIGV : Rcur[g];
                const float diff = st5[g] - spw[c & 255];
                const float d = diff * diff;
                const float mn = fminf(dg, fminf(upv, lf));
                const float mnK = mn * KLOG2E;
                const float ea = ex2f(fmaf(dg, NEGK, mnK));
                const float eb = ex2f(fmaf(upv, NEGK, mnK));
                const float ec = ex2f(fmaf(lf, NEGK, mnK));
                const float ssum = ea + eb + ec;
                const float r = fmaf(NGLN2, lg2f(ssum), d + mn);
                const float inv = rcpf(ssum);
                st_pred2(act, pw + 32 * g, ea * inv, eb * inv);
                uprev[g] = upv;
                Rcur[g] = r;
            }
            pw += min(min(s + 1, 159), 318 - s);  // A(s+1) - A(s)
        }
    }
    if (lane == 31) g_sdtw[prob] = Rcur[4];  // R[N-1][N-1]

    __threadfence_block();  // order weight stores before cp.async readback

    // ---------------- backward: branch-free reverse wavefront ----------------
    // Ring slot for diag d holds entries k = ri - rlo(d) at [slot+1+k];
    // front pad absorbs the clamped -1 index (always select-gated).
    float2* const ringw = &ring[w][0][0];
    auto prefetch = [&](int d, int dof) {
        const float2* src = probbase + dof + lane;
        uint32_t dst = smem_u32(ringw + (d & 7) * SLOT + 1 + lane);
#pragma unroll
        for (int k = 0; k < 5; ++k)
            cpa8(dst + (uint32_t)(k * 32 * sizeof(float2)), src + k * 32);
        CP_COMMIT();
    };
#pragma unroll
    for (int d = NDIAG - 1; d >= NDIAG - 7; --d) prefetch(d, doffs(d));

    float Ecur[5], dprev[5], ddf[5];
#pragma unroll
    for (int g = 0; g < 5; ++g) {
        Ecur[g] = 0.0f;
        dprev[g] = 0.0f;
        ddf[g] = (float)(2 * (lane + 32 * g) - (NDIAG - 2));  // ri-c at sb=317
    }
    Ecur[4] = (lane == 31) ? 1.0f : 0.0f;  // seed E[N-1][N-1] (sb = 318)
    float acc = 0.0f;                       // seed contributes 0 (ri == c)

    int pf = NDIAG - 8;       // 311: next diag to prefetch
    int pfD = doffs(NDIAG - 8);

    for (int sb = NDIAG - 2; sb >= 0; --sb) {
        CP_WAIT6();  // diag sb+1 (and older) staged
        float sd[5];
#pragma unroll
        for (int g = 0; g < 5; ++g)
            sd[g] = __shfl_sync(FULLM, Ecur[g], (lane + 1) & 31);
        const float2* ch1 = ringw + ((sb + 1) & 7) * SLOT + 1;
        const float2* ch2 = ringw + ((sb + 2) & 7) * SLOT + 1;
        const int b1 = lane - max(sb - 158, 0);      // ri - rlo(sb+1) - 32g
        const int b2 = lane + 1 - max(sb - 157, 0);  // ri+1 - rlo(sb+2) - 32g
#pragma unroll
        for (int g = 0; g < 5; ++g) {
            const int ri = lane + 32 * g;
            const int c = sb - ri;
            const unsigned act = (unsigned)c < (unsigned)N;
            const float echild =
                (lane < 31) ? sd[g] : ((g < 4) ? sd[g + 1] : 0.0f);
            const int i0 = max(b1 + 32 * g, -1);
            const int i2 = max(b2 + 32 * g, -1);
            const float2 f = ch1[i0 + 1];  // child (ri+1, c):   wu
            const float2 q = ch1[i0];      // child (ri, c+1):   wl
            const float2 h = ch2[i2];      // child (ri+1, c+1): wd
            const bool rok = (ri + 1 < N);
            const bool cok = (c + 1 < N);
            const float wuv = rok ? f.y : 0.0f;
            const float wlv = cok ? (1.0f - q.x - q.y) : 0.0f;
            const float wdv = (rok && cok) ? h.x : 0.0f;
            float ev = echild * wuv;
            ev = fmaf(dprev[g], wdv, ev);
            ev = fmaf(Ecur[g], wlv, ev);
            dprev[g] = echild;
            Ecur[g] = ev;
            const float evm = act ? ev : 0.0f;
            acc = fmaf(evm * ddf[g], ddf[g], acc);
            ddf[g] += 1.0f;
        }
        prefetch(pf, pfD);
        const int npf = max(pf - 1, 0);
        pfD -= (pf != npf) ? ((npf <= 159) ? npf + 1 : 319 - npf) : 0;
        pf = npf;
    }

    // warp reduction of temporal accumulator
#pragma unroll
    for (int o = 16; o; o >>= 1) acc += __shfl_down_sync(FULLM, acc, o);
    if (lane == 0) g_lt[prob] = acc * (1.0f / (float)NCELLS);

    // ---------------- fused final reduction (last block) ----------------
    __threadfence();  // publish g_sdtw / g_lt
    __syncthreads();
    if (threadIdx.x == 0)
        s_last = (atomicAdd(&g_ticket, 1u) == (unsigned)(gridDim.x - 1));
    __syncthreads();
    if (s_last) {
        const int b = threadIdx.x;  // 0..127; only 0..63 carry a batch
        float ls = 0.0f, lt = 0.0f;
        if (b < BATCH) {
#pragma unroll
            for (int c = 0; c < CH; ++c) {
                ls += g_sdtw[b * CH + c];
                lt += g_lt[b * CH + c];
            }
            ls *= (1.0f / (float)CH);
            lt *= (1.0f / (float)CH);
            out[1 + b] = ls;          // loss_shape
            out[1 + BATCH + b] = lt;  // loss_temporal
        }
        float v = (b < BATCH) ? (0.5f * ls + 0.5f * lt) : 0.0f;
#pragma unroll
        for (int o = 16; o; o >>= 1) v += __shfl_down_sync(FULLM, v, o);
        if ((threadIdx.x & 31) == 0) ws[threadIdx.x >> 5] = v;
        __syncthreads();
        if (threadIdx.x == 0) {
            out[0] = (ws[0] + ws[1]) * (1.0f / (float)BATCH);  // loss
            g_ticket = 0;  // reset for next graph replay
        }
    }
}

extern "C" void kernel_launch(void* const* d_in, const int* in_sizes, int n_in,
                              void* d_out, int out_size) {
    const float* input = (const float*)d_in[0];
    const float* target = (const float*)d_in[1];
    float* out = (float*)d_out;
    dtw_warp_kernel<<<BC / 4, 128>>>(input, target, out);
}